// round 3
// baseline (speedup 1.0000x reference)
#include <cuda_runtime.h>
#include <cuda_fp16.h>

#define BB 2
#define NN 65536
#define KK 16
#define DD 32

typedef unsigned long long u64;

__device__ __forceinline__ u64 pk2(float lo, float hi) {
    u64 r; asm("mov.b64 %0,{%1,%2};" : "=l"(r) : "f"(lo), "f"(hi)); return r;
}
__device__ __forceinline__ void up2(u64 v, float& a, float& b) {
    asm("mov.b64 {%0,%1},%2;" : "=f"(a), "=f"(b) : "l"(v));
}
__device__ __forceinline__ u64 ffma2(u64 a, u64 b, u64 c) {
    u64 d; asm("fma.rn.f32x2 %0,%1,%2,%3;" : "=l"(d) : "l"(a), "l"(b), "l"(c)); return d;
}

// Scratch (device globals; no allocation allowed)
__device__ uint4 g_preh4[BB * NN * 4];   // pre[b][n][32] as fp16 rows (8 MB, L2-resident)
__device__ float g_part[128 * 64];       // per-block TNet partial maxima
__device__ float g_tmat[BB * 9];
__device__ int   g_idx64;                // 1 if neigh_idx is int64, else 0

// ---------------------------------------------------------------------------
// K1: TNet pointwise 3->16->64 (f32x2 FMA) + max over 4 pts/thread + reduce.
// ---------------------------------------------------------------------------
__global__ void __launch_bounds__(256) k_tnet_reduce(
    const float* __restrict__ xyz,
    const float* __restrict__ tW1, const float* __restrict__ ts1, const float* __restrict__ tb1,
    const float* __restrict__ tW2, const float* __restrict__ ts2, const float* __restrict__ tb2)
{
    __shared__ float4 sW2f4[256];                // 16 rows x 64 cols
    __shared__ float  sW1[48], sS1[16], sB1[16], sS2[64], sB2[64];
    __shared__ float  warpmax[8][64];
    int t = threadIdx.x;
    sW2f4[t] = ((const float4*)tW2)[t];
    if (t < 48) sW1[t] = tW1[t];
    if (t < 16) { sS1[t] = ts1[t]; sB1[t] = tb1[t]; }
    if (t < 64) { sS2[t] = ts2[t]; sB2[t] = tb2[t]; }
    __syncthreads();
    const ulonglong2* w2u = (const ulonglong2*)sW2f4;

    float m[64];
#pragma unroll
    for (int c = 0; c < 64; c++) m[c] = 0.f;

    int base = blockIdx.x * 1024;
#pragma unroll
    for (int r = 0; r < 4; r++) {
        int gp = base + r * 256 + t;
        float x0 = xyz[gp * 3 + 0], x1 = xyz[gp * 3 + 1], x2 = xyz[gp * 3 + 2];
        float h1[16];
#pragma unroll
        for (int c = 0; c < 16; c++) {
            float a = x0 * sW1[c] + x1 * sW1[16 + c] + x2 * sW1[32 + c];
            h1[c] = fmaxf(a * sS1[c] + sB1[c], 0.f);
        }
        u64 h2[32];
#pragma unroll
        for (int c = 0; c < 32; c++) h2[c] = 0ull;
#pragma unroll
        for (int i = 0; i < 16; i++) {
            u64 vv = pk2(h1[i], h1[i]);
#pragma unroll
            for (int c4 = 0; c4 < 16; c4++) {
                ulonglong2 w = w2u[i * 16 + c4];
                h2[2 * c4 + 0] = ffma2(vv, w.x, h2[2 * c4 + 0]);
                h2[2 * c4 + 1] = ffma2(vv, w.y, h2[2 * c4 + 1]);
            }
        }
#pragma unroll
        for (int c2 = 0; c2 < 32; c2++) {
            float a, b; up2(h2[c2], a, b);
            int c = 2 * c2;
            m[c]     = fmaxf(m[c],     fmaxf(a * sS2[c]     + sB2[c],     0.f));
            m[c + 1] = fmaxf(m[c + 1], fmaxf(b * sS2[c + 1] + sB2[c + 1], 0.f));
        }
    }

#pragma unroll
    for (int c = 0; c < 64; c++) {
#pragma unroll
        for (int off = 16; off; off >>= 1)
            m[c] = fmaxf(m[c], __shfl_xor_sync(0xffffffffu, m[c], off));
    }
    int w = t >> 5, lane = t & 31;
    if (lane == 0) {
#pragma unroll
        for (int c = 0; c < 64; c++) warpmax[w][c] = m[c];
    }
    __syncthreads();
    if (t < 64) {
        float v = warpmax[0][t];
#pragma unroll
        for (int ww = 1; ww < 8; ww++) v = fmaxf(v, warpmax[ww][t]);
        g_part[blockIdx.x * 64 + t] = v;
    }
}

// ---------------------------------------------------------------------------
// K2: reduce partials, TNet head 64 -> 16 -> 9 (+identity); idx dtype detect.
// ---------------------------------------------------------------------------
__global__ void k_tnet_head(
    const float* __restrict__ tW3, const float* __restrict__ ts3, const float* __restrict__ tb3,
    const float* __restrict__ tW4, const float* __restrict__ tb4,
    const int* __restrict__ nidx)
{
    __shared__ float hmax[64], h3s[16];
    int b = blockIdx.x, t = threadIdx.x;
    if (t < 64) {
        float v = 0.f;
        for (int j = 0; j < 64; j++) v = fmaxf(v, g_part[(b * 64 + j) * 64 + t]);
        hmax[t] = v;
    }
    __syncthreads();
    if (t < 16) {
        float a = 0.f;
        for (int i = 0; i < 64; i++) a += hmax[i] * tW3[i * 16 + t];
        h3s[t] = fmaxf(a * ts3[t] + tb3[t], 0.f);
    }
    __syncthreads();
    if (t < 9) {
        float a = 0.f;
        for (int i = 0; i < 16; i++) a += h3s[i] * tW4[i * 9 + t];
        a += tb4[t];
        if (t == 0 || t == 4 || t == 8) a += 1.0f;   // + eye(3)
        g_tmat[b * 9 + t] = a;
    }
    if (b == 0 && t == 63) {
        int z = 0;
#pragma unroll
        for (int i = 1; i < 16; i += 2) z |= nidx[i];
        g_idx64 = (z == 0) ? 1 : 0;
    }
}

// ---------------------------------------------------------------------------
// K3: fused per-point MLPs -> pre[b,n,32] fp16. f32x2 FMA throughout.
// 1024 blocks x 128 threads, 1 point/thread.
// ---------------------------------------------------------------------------
__global__ void __launch_bounds__(128) k_pointwise(
    const float* __restrict__ feature, const float* __restrict__ xyz,
    const float* __restrict__ W1, const float* __restrict__ s1, const float* __restrict__ b1,
    const float* __restrict__ W2, const float* __restrict__ s2, const float* __restrict__ b2,
    const float* __restrict__ W3, const float* __restrict__ s3, const float* __restrict__ b3)
{
    __shared__ float4 sW2f4[256];        // W2 32x32
    __shared__ float4 sW3f4[256];        // W3 rows 0..31
    __shared__ float4 sW3x4[24];         // W3 rows 32..34
    __shared__ float  sS2[32], sB2[32], sS3[32], sB3[32];
    __shared__ float  sW1[9], sTM[9], sS1[3], sB1[3];
    __shared__ uint4  sStage[640];       // 128 pts x 4 uint4, stride 5
    int t   = threadIdx.x;
    int gp0 = blockIdx.x * 128;
    int b   = gp0 >> 16;
    { const float4* W2v = (const float4*)W2;
      sW2f4[t] = W2v[t]; sW2f4[128 + t] = W2v[128 + t]; }
    { const float4* W3v = (const float4*)W3;
      sW3f4[t] = W3v[t]; sW3f4[128 + t] = W3v[128 + t];
      if (t < 24) sW3x4[t] = W3v[256 + t]; }
    if (t < 32) { sS2[t] = s2[t]; sB2[t] = b2[t]; sS3[t] = s3[t]; sB3[t] = b3[t]; }
    if (t < 9)  { sW1[t] = W1[t]; sTM[t] = g_tmat[b * 9 + t]; }
    if (t < 3)  { sS1[t] = s1[t]; sB1[t] = b1[t]; }
    __syncthreads();
    const ulonglong2* w2u  = (const ulonglong2*)sW2f4;
    const ulonglong2* w3u  = (const ulonglong2*)sW3f4;
    const ulonglong2* w3xu = (const ulonglong2*)sW3x4;

    int gp = gp0 + t;
    int n  = gp & (NN - 1);

    // f_xyz = relu(((xyz @ t3x3) @ W1) * s1 + b1)
    float x0 = xyz[gp * 3 + 0], x1 = xyz[gp * 3 + 1], x2 = xyz[gp * 3 + 2];
    float v0 = x0 * sTM[0] + x1 * sTM[3] + x2 * sTM[6];
    float v1 = x0 * sTM[1] + x1 * sTM[4] + x2 * sTM[7];
    float v2 = x0 * sTM[2] + x1 * sTM[5] + x2 * sTM[8];
    float fx0 = fmaxf((v0 * sW1[0] + v1 * sW1[3] + v2 * sW1[6]) * sS1[0] + sB1[0], 0.f);
    float fx1 = fmaxf((v0 * sW1[1] + v1 * sW1[4] + v2 * sW1[7]) * sS1[1] + sB1[1], 0.f);
    float fx2 = fmaxf((v0 * sW1[2] + v1 * sW1[5] + v2 * sW1[8]) * sS1[2] + sB1[2], 0.f);

    // f_nei = relu((feat @ W2) * s2 + b2)
    const float* fbase = feature + (size_t)b * DD * NN + n;
    u64 acc2[16];
#pragma unroll
    for (int c = 0; c < 16; c++) acc2[c] = 0ull;
#pragma unroll
    for (int i = 0; i < 32; i++) {
        float v = fbase[(size_t)i * NN];
        u64 vv = pk2(v, v);
#pragma unroll
        for (int c4 = 0; c4 < 8; c4++) {
            ulonglong2 w = w2u[i * 8 + c4];
            acc2[2 * c4 + 0] = ffma2(vv, w.x, acc2[2 * c4 + 0]);
            acc2[2 * c4 + 1] = ffma2(vv, w.y, acc2[2 * c4 + 1]);
        }
    }
    float fn[32];
#pragma unroll
    for (int c2 = 0; c2 < 16; c2++) {
        float a, bb; up2(acc2[c2], a, bb);
        fn[2 * c2]     = fmaxf(a  * sS2[2 * c2]     + sB2[2 * c2],     0.f);
        fn[2 * c2 + 1] = fmaxf(bb * sS2[2 * c2 + 1] + sB2[2 * c2 + 1], 0.f);
    }

    // pre = relu((concat(fn, fx) @ W3) * s3 + b3)
#pragma unroll
    for (int c = 0; c < 16; c++) acc2[c] = 0ull;
#pragma unroll
    for (int i = 0; i < 32; i++) {
        u64 vv = pk2(fn[i], fn[i]);
#pragma unroll
        for (int c4 = 0; c4 < 8; c4++) {
            ulonglong2 w = w3u[i * 8 + c4];
            acc2[2 * c4 + 0] = ffma2(vv, w.x, acc2[2 * c4 + 0]);
            acc2[2 * c4 + 1] = ffma2(vv, w.y, acc2[2 * c4 + 1]);
        }
    }
    {
        u64 vx0 = pk2(fx0, fx0), vx1 = pk2(fx1, fx1), vx2 = pk2(fx2, fx2);
#pragma unroll
        for (int c4 = 0; c4 < 8; c4++) {
            ulonglong2 wa = w3xu[c4], wb = w3xu[8 + c4], wc = w3xu[16 + c4];
            acc2[2 * c4 + 0] = ffma2(vx0, wa.x, acc2[2 * c4 + 0]);
            acc2[2 * c4 + 1] = ffma2(vx0, wa.y, acc2[2 * c4 + 1]);
            acc2[2 * c4 + 0] = ffma2(vx1, wb.x, acc2[2 * c4 + 0]);
            acc2[2 * c4 + 1] = ffma2(vx1, wb.y, acc2[2 * c4 + 1]);
            acc2[2 * c4 + 0] = ffma2(vx2, wc.x, acc2[2 * c4 + 0]);
            acc2[2 * c4 + 1] = ffma2(vx2, wc.y, acc2[2 * c4 + 1]);
        }
    }
    unsigned uh[16];
#pragma unroll
    for (int c2 = 0; c2 < 16; c2++) {
        float a, bb; up2(acc2[c2], a, bb);
        a  = fmaxf(a  * sS3[2 * c2]     + sB3[2 * c2],     0.f);
        bb = fmaxf(bb * sS3[2 * c2 + 1] + sB3[2 * c2 + 1], 0.f);
        __half2 h = __floats2half2_rn(a, bb);
        uh[c2] = *reinterpret_cast<unsigned*>(&h);
    }
#pragma unroll
    for (int q = 0; q < 4; q++) {
        uint4 o;
        o.x = uh[q * 4 + 0]; o.y = uh[q * 4 + 1]; o.z = uh[q * 4 + 2]; o.w = uh[q * 4 + 3];
        sStage[t * 5 + q] = o;
    }
    __syncthreads();

    // coalesced uint4 writeout
    uint4* outp = g_preh4 + (size_t)gp0 * 4;
#pragma unroll
    for (int r = 0; r < 4; r++) {
        int i = r * 128 + t;             // i = p*4 + q
        outp[i] = sStage[(i >> 2) * 5 + (i & 3)];
    }
}

// ---------------------------------------------------------------------------
// K4: fp16 gather-max (4 lanes/point, uint4=16B each -> 8 pts/warp-instr),
// then final 64->32 MLP with f32x2 FMA and 2-point weight amortization.
// 128 points/block, 512 threads.
// ---------------------------------------------------------------------------
__global__ void __launch_bounds__(512) k_gather_final(
    const float* __restrict__ feature, const int* __restrict__ nidx,
    const float* __restrict__ W4, const float* __restrict__ s4, const float* __restrict__ b4,
    float* __restrict__ out)
{
    __shared__ float4 sW4f4[512];        // W4 64x32
    __shared__ float  sS4[32], sB4[32];
    __shared__ float  featS[128 * 36];
    __shared__ float  fcatS[128 * 36];
    __shared__ float  sOut[128 * 33];
    int t = threadIdx.x;
    sW4f4[t] = ((const float4*)W4)[t];
    if (t < 32) { sS4[t] = s4[t]; sB4[t] = b4[t]; }

    int gp0 = blockIdx.x * 128;
    int b   = gp0 >> 16;
    int n0  = gp0 & (NN - 1);

    // stage feat (coalesced along n)
    const float* fbase = feature + (size_t)b * DD * NN + n0;
#pragma unroll
    for (int r = 0; r < 8; r++) {
        int i = r * 512 + t;             // i = c*128 + p
        int c = i >> 7, p = i & 127;
        featS[p * 36 + c] = fbase[(size_t)c * NN + p];
    }

    // cooperative gather-max: 4 lanes/point, each lane owns 8 fp16 channels
    {
        int lane = t & 31;
        int warp = t >> 5;
        int cl   = lane & 3;
        int p    = warp * 8 + (lane >> 2);
        int gp   = gp0 + p;
        int mul  = g_idx64 ? 2 : 1;
        const int* ib = nidx + (size_t)gp * KK * mul;
        int j0 = ib[cl * mul];
        int j1 = ib[(cl + 4) * mul];
        int j2 = ib[(cl + 8) * mul];
        int j3 = ib[(cl + 12) * mul];
        const uint4* pre4 = g_preh4 + (size_t)b * NN * 4;
        __half2 a0 = __half2half2(__ushort_as_half(0));
        __half2 a1 = a0, a2 = a0, a3 = a0;   // pre >= 0, so 0-init exact
#pragma unroll
        for (int k = 0; k < KK; k++) {
            int jr = (k < 8) ? ((k < 4) ? j0 : j1) : ((k < 12) ? j2 : j3);
            int j  = __shfl_sync(0xffffffffu, jr, k & 3, 4);
            uint4 v = pre4[(size_t)j * 4 + cl];
            a0 = __hmax2(a0, *reinterpret_cast<__half2*>(&v.x));
            a1 = __hmax2(a1, *reinterpret_cast<__half2*>(&v.y));
            a2 = __hmax2(a2, *reinterpret_cast<__half2*>(&v.z));
            a3 = __hmax2(a3, *reinterpret_cast<__half2*>(&v.w));
        }
        float2 f0 = __half22float2(a0), f1 = __half22float2(a1);
        float2 f2 = __half22float2(a2), f3 = __half22float2(a3);
        float4* row = (float4*)(fcatS + p * 36);
        row[cl * 2 + 0] = make_float4(f0.x, f0.y, f1.x, f1.y);
        row[cl * 2 + 1] = make_float4(f2.x, f2.y, f3.x, f3.y);
    }
    __syncthreads();

    // final MLP: 8 ch-group threads x 2 points each (weights read once per pair)
    {
        int pp = (t >> 3) * 2, g = t & 7;
        const ulonglong2* w4u = (const ulonglong2*)sW4f4;
        const float4* fS0 = (const float4*)(featS + pp * 36);
        const float4* fS1 = (const float4*)(featS + (pp + 1) * 36);
        const float4* cS0 = (const float4*)(fcatS + pp * 36);
        const float4* cS1 = (const float4*)(fcatS + (pp + 1) * 36);
        u64 p0lo = 0ull, p0hi = 0ull, p1lo = 0ull, p1hi = 0ull;
#pragma unroll
        for (int i4 = 0; i4 < 16; i4++) {
            float4 f0 = (i4 < 8) ? fS0[i4] : cS0[i4 - 8];
            float4 f1 = (i4 < 8) ? fS1[i4] : cS1[i4 - 8];
            ulonglong2 w0 = w4u[(i4 * 4 + 0) * 8 + g];
            ulonglong2 w1 = w4u[(i4 * 4 + 1) * 8 + g];
            ulonglong2 w2 = w4u[(i4 * 4 + 2) * 8 + g];
            ulonglong2 w3 = w4u[(i4 * 4 + 3) * 8 + g];
            u64 v;
            v = pk2(f0.x, f0.x); p0lo = ffma2(v, w0.x, p0lo); p0hi = ffma2(v, w0.y, p0hi);
            v = pk2(f1.x, f1.x); p1lo = ffma2(v, w0.x, p1lo); p1hi = ffma2(v, w0.y, p1hi);
            v = pk2(f0.y, f0.y); p0lo = ffma2(v, w1.x, p0lo); p0hi = ffma2(v, w1.y, p0hi);
            v = pk2(f1.y, f1.y); p1lo = ffma2(v, w1.x, p1lo); p1hi = ffma2(v, w1.y, p1hi);
            v = pk2(f0.z, f0.z); p0lo = ffma2(v, w2.x, p0lo); p0hi = ffma2(v, w2.y, p0hi);
            v = pk2(f1.z, f1.z); p1lo = ffma2(v, w2.x, p1lo); p1hi = ffma2(v, w2.y, p1hi);
            v = pk2(f0.w, f0.w); p0lo = ffma2(v, w3.x, p0lo); p0hi = ffma2(v, w3.y, p0hi);
            v = pk2(f1.w, f1.w); p1lo = ffma2(v, w3.x, p1lo); p1hi = ffma2(v, w3.y, p1hi);
        }
        int c0 = g * 4;
        float a, bb;
        up2(p0lo, a, bb);
        sOut[pp * 33 + c0 + 0] = fmaxf(a  * sS4[c0 + 0] + sB4[c0 + 0], 0.f);
        sOut[pp * 33 + c0 + 1] = fmaxf(bb * sS4[c0 + 1] + sB4[c0 + 1], 0.f);
        up2(p0hi, a, bb);
        sOut[pp * 33 + c0 + 2] = fmaxf(a  * sS4[c0 + 2] + sB4[c0 + 2], 0.f);
        sOut[pp * 33 + c0 + 3] = fmaxf(bb * sS4[c0 + 3] + sB4[c0 + 3], 0.f);
        up2(p1lo, a, bb);
        sOut[(pp + 1) * 33 + c0 + 0] = fmaxf(a  * sS4[c0 + 0] + sB4[c0 + 0], 0.f);
        sOut[(pp + 1) * 33 + c0 + 1] = fmaxf(bb * sS4[c0 + 1] + sB4[c0 + 1], 0.f);
        up2(p1hi, a, bb);
        sOut[(pp + 1) * 33 + c0 + 2] = fmaxf(a  * sS4[c0 + 2] + sB4[c0 + 2], 0.f);
        sOut[(pp + 1) * 33 + c0 + 3] = fmaxf(bb * sS4[c0 + 3] + sB4[c0 + 3], 0.f);
    }
    __syncthreads();

    // coalesced writeout
    float* ob = out + (size_t)b * DD * NN + n0;
#pragma unroll
    for (int r = 0; r < 8; r++) {
        int i = r * 512 + t;             // i = c*128 + p
        int c = i >> 7, pw = i & 127;
        ob[(size_t)c * NN + pw] = sOut[pw * 33 + c];
    }
}

// ---------------------------------------------------------------------------

extern "C" void kernel_launch(void* const* d_in, const int* in_sizes, int n_in,
                              void* d_out, int out_size) {
    const float* feature = (const float*)d_in[0];
    const float* xyz     = (const float*)d_in[1];
    const int*   nidx    = (const int*)d_in[2];
    const float* tW1 = (const float*)d_in[3];  const float* ts1 = (const float*)d_in[4];  const float* tb1 = (const float*)d_in[5];
    const float* tW2 = (const float*)d_in[6];  const float* ts2 = (const float*)d_in[7];  const float* tb2 = (const float*)d_in[8];
    const float* tW3 = (const float*)d_in[9];  const float* ts3 = (const float*)d_in[10]; const float* tb3 = (const float*)d_in[11];
    const float* tW4 = (const float*)d_in[12]; const float* tb4 = (const float*)d_in[13];
    const float* W1  = (const float*)d_in[14]; const float* s1  = (const float*)d_in[15]; const float* b1  = (const float*)d_in[16];
    const float* W2  = (const float*)d_in[17]; const float* s2  = (const float*)d_in[18]; const float* b2  = (const float*)d_in[19];
    const float* W3  = (const float*)d_in[20]; const float* s3  = (const float*)d_in[21]; const float* b3  = (const float*)d_in[22];
    const float* W4  = (const float*)d_in[23]; const float* s4  = (const float*)d_in[24]; const float* b4  = (const float*)d_in[25];
    float* out = (float*)d_out;

    k_tnet_reduce<<<128, 256>>>(xyz, tW1, ts1, tb1, tW2, ts2, tb2);
    k_tnet_head<<<BB, 64>>>(tW3, ts3, tb3, tW4, tb4, nidx);
    k_pointwise<<<(BB * NN) / 128, 128>>>(feature, xyz, W1, s1, b1, W2, s2, b2, W3, s3, b3);
    k_gather_final<<<(BB * NN) / 128, 512>>>(feature, nidx, W4, s4, b4, out);
}

// round 4
// speedup vs baseline: 1.3169x; 1.3169x over previous
#include <cuda_runtime.h>
#include <cuda_fp16.h>

#define BB 2
#define NN 65536
#define KK 16
#define DD 32

typedef unsigned long long u64;

__device__ __forceinline__ u64 pk2(float lo, float hi) {
    u64 r; asm("mov.b64 %0,{%1,%2};" : "=l"(r) : "f"(lo), "f"(hi)); return r;
}
__device__ __forceinline__ void up2(u64 v, float& a, float& b) {
    asm("mov.b64 {%0,%1},%2;" : "=f"(a), "=f"(b) : "l"(v));
}
__device__ __forceinline__ u64 ffma2(u64 a, u64 b, u64 c) {
    u64 d; asm("fma.rn.f32x2 %0,%1,%2,%3;" : "=l"(d) : "l"(a), "l"(b), "l"(c)); return d;
}

// Scratch (device globals; no allocation allowed)
__device__ uint4 g_preh4[BB * NN * 4];   // pre[b][n][32] fp16 rows (8 MB, L2-resident)
__device__ float g_part[128 * 64];       // per-block TNet partial maxima
__device__ float g_tmat[BB * 9];
__device__ int   g_idx64;                // 1 if neigh_idx is int64, else 0

// ---------------------------------------------------------------------------
// K1: TNet pointwise 3->16->64 + max over 4 points/thread + warp/block reduce.
// (Round-2 plain float4 FFMA formulation — measured fast.)
// ---------------------------------------------------------------------------
__global__ void __launch_bounds__(256) k_tnet_reduce(
    const float* __restrict__ xyz,
    const float* __restrict__ tW1, const float* __restrict__ ts1, const float* __restrict__ tb1,
    const float* __restrict__ tW2, const float* __restrict__ ts2, const float* __restrict__ tb2)
{
    __shared__ float4 sW2f4[256];                // 16 rows x 64 cols as float4
    __shared__ float  sW1[48], sS1[16], sB1[16], sS2[64], sB2[64];
    __shared__ float  warpmax[8][64];
    int t = threadIdx.x;
    sW2f4[t] = ((const float4*)tW2)[t];
    if (t < 48) sW1[t] = tW1[t];
    if (t < 16) { sS1[t] = ts1[t]; sB1[t] = tb1[t]; }
    if (t < 64) { sS2[t] = ts2[t]; sB2[t] = tb2[t]; }
    __syncthreads();

    float m[64];
#pragma unroll
    for (int c = 0; c < 64; c++) m[c] = 0.f;

    int base = blockIdx.x * 1024;
#pragma unroll
    for (int r = 0; r < 4; r++) {
        int gp = base + r * 256 + t;
        float x0 = xyz[gp * 3 + 0], x1 = xyz[gp * 3 + 1], x2 = xyz[gp * 3 + 2];
        float h1[16];
#pragma unroll
        for (int c = 0; c < 16; c++) {
            float a = x0 * sW1[c] + x1 * sW1[16 + c] + x2 * sW1[32 + c];
            h1[c] = fmaxf(a * sS1[c] + sB1[c], 0.f);
        }
        float h2[64];
#pragma unroll
        for (int c = 0; c < 64; c++) h2[c] = 0.f;
#pragma unroll
        for (int i = 0; i < 16; i++) {
            float v = h1[i];
#pragma unroll
            for (int c4 = 0; c4 < 16; c4++) {
                float4 w = sW2f4[i * 16 + c4];
                h2[c4 * 4 + 0] += v * w.x; h2[c4 * 4 + 1] += v * w.y;
                h2[c4 * 4 + 2] += v * w.z; h2[c4 * 4 + 3] += v * w.w;
            }
        }
#pragma unroll
        for (int c = 0; c < 64; c++)
            m[c] = fmaxf(m[c], fmaxf(h2[c] * sS2[c] + sB2[c], 0.f));
    }

#pragma unroll
    for (int c = 0; c < 64; c++) {
#pragma unroll
        for (int off = 16; off; off >>= 1)
            m[c] = fmaxf(m[c], __shfl_xor_sync(0xffffffffu, m[c], off));
    }
    int w = t >> 5, lane = t & 31;
    if (lane == 0) {
#pragma unroll
        for (int c = 0; c < 64; c++) warpmax[w][c] = m[c];
    }
    __syncthreads();
    if (t < 64) {
        float v = warpmax[0][t];
#pragma unroll
        for (int ww = 1; ww < 8; ww++) v = fmaxf(v, warpmax[ww][t]);
        g_part[blockIdx.x * 64 + t] = v;
    }
}

// ---------------------------------------------------------------------------
// K2: reduce partials, TNet head 64 -> 16 -> 9 (+identity); idx dtype detect.
// ---------------------------------------------------------------------------
__global__ void k_tnet_head(
    const float* __restrict__ tW3, const float* __restrict__ ts3, const float* __restrict__ tb3,
    const float* __restrict__ tW4, const float* __restrict__ tb4,
    const int* __restrict__ nidx)
{
    __shared__ float hmax[64], h3s[16];
    int b = blockIdx.x, t = threadIdx.x;
    if (t < 64) {
        float v = 0.f;
        for (int j = 0; j < 64; j++) v = fmaxf(v, g_part[(b * 64 + j) * 64 + t]);
        hmax[t] = v;
    }
    __syncthreads();
    if (t < 16) {
        float a = 0.f;
        for (int i = 0; i < 64; i++) a += hmax[i] * tW3[i * 16 + t];
        h3s[t] = fmaxf(a * ts3[t] + tb3[t], 0.f);
    }
    __syncthreads();
    if (t < 9) {
        float a = 0.f;
        for (int i = 0; i < 16; i++) a += h3s[i] * tW4[i * 9 + t];
        a += tb4[t];
        if (t == 0 || t == 4 || t == 8) a += 1.0f;   // + eye(3)
        g_tmat[b * 9 + t] = a;
    }
    if (b == 0 && t == 63) {
        int z = 0;
#pragma unroll
        for (int i = 1; i < 16; i += 2) z |= nidx[i];
        g_idx64 = (z == 0) ? 1 : 0;
    }
}

// ---------------------------------------------------------------------------
// K3: fused per-point MLPs -> pre[b,n,32] fp16. Round-2 float4 FFMA math,
// fp16 packed output. 1024 blocks x 128 threads, 1 point/thread.
// ---------------------------------------------------------------------------
__global__ void __launch_bounds__(128) k_pointwise(
    const float* __restrict__ feature, const float* __restrict__ xyz,
    const float* __restrict__ W1, const float* __restrict__ s1, const float* __restrict__ b1,
    const float* __restrict__ W2, const float* __restrict__ s2, const float* __restrict__ b2,
    const float* __restrict__ W3, const float* __restrict__ s3, const float* __restrict__ b3)
{
    __shared__ float4 sW2f4[256];        // W2 32x32
    __shared__ float4 sW3f4[256];        // W3 rows 0..31
    __shared__ float4 sW3x4[24];         // W3 rows 32..34 (xyz part)
    __shared__ float  sS2[32], sB2[32], sS3[32], sB3[32];
    __shared__ float  sW1[9], sTM[9], sS1[3], sB1[3];
    __shared__ uint4  sStage[640];       // 128 pts x 4 uint4, stride 5
    int t   = threadIdx.x;
    int gp0 = blockIdx.x * 128;
    int b   = gp0 >> 16;
    { const float4* W2v = (const float4*)W2;
      sW2f4[t] = W2v[t]; sW2f4[128 + t] = W2v[128 + t]; }
    { const float4* W3v = (const float4*)W3;
      sW3f4[t] = W3v[t]; sW3f4[128 + t] = W3v[128 + t];
      if (t < 24) sW3x4[t] = W3v[256 + t]; }
    if (t < 32) { sS2[t] = s2[t]; sB2[t] = b2[t]; sS3[t] = s3[t]; sB3[t] = b3[t]; }
    if (t < 9)  { sW1[t] = W1[t]; sTM[t] = g_tmat[b * 9 + t]; }
    if (t < 3)  { sS1[t] = s1[t]; sB1[t] = b1[t]; }
    __syncthreads();

    int gp = gp0 + t;
    int n  = gp & (NN - 1);

    // f_xyz = relu(((xyz @ t3x3) @ W1) * s1 + b1)
    float x0 = xyz[gp * 3 + 0], x1 = xyz[gp * 3 + 1], x2 = xyz[gp * 3 + 2];
    float v0 = x0 * sTM[0] + x1 * sTM[3] + x2 * sTM[6];
    float v1 = x0 * sTM[1] + x1 * sTM[4] + x2 * sTM[7];
    float v2 = x0 * sTM[2] + x1 * sTM[5] + x2 * sTM[8];
    float fx0 = fmaxf((v0 * sW1[0] + v1 * sW1[3] + v2 * sW1[6]) * sS1[0] + sB1[0], 0.f);
    float fx1 = fmaxf((v0 * sW1[1] + v1 * sW1[4] + v2 * sW1[7]) * sS1[1] + sB1[1], 0.f);
    float fx2 = fmaxf((v0 * sW1[2] + v1 * sW1[5] + v2 * sW1[8]) * sS1[2] + sB1[2], 0.f);

    // f_nei = relu((feat @ W2) * s2 + b2)
    const float* fbase = feature + (size_t)b * DD * NN + n;
    float acc[32];
#pragma unroll
    for (int c = 0; c < 32; c++) acc[c] = 0.f;
#pragma unroll
    for (int i = 0; i < 32; i++) {
        float v = fbase[(size_t)i * NN];
#pragma unroll
        for (int c4 = 0; c4 < 8; c4++) {
            float4 w = sW2f4[i * 8 + c4];
            acc[c4 * 4 + 0] += v * w.x; acc[c4 * 4 + 1] += v * w.y;
            acc[c4 * 4 + 2] += v * w.z; acc[c4 * 4 + 3] += v * w.w;
        }
    }
    float fn[32];
#pragma unroll
    for (int c = 0; c < 32; c++) fn[c] = fmaxf(acc[c] * sS2[c] + sB2[c], 0.f);

    // pre = relu((concat(fn, fx) @ W3) * s3 + b3)
#pragma unroll
    for (int c = 0; c < 32; c++) acc[c] = 0.f;
#pragma unroll
    for (int i = 0; i < 32; i++) {
        float v = fn[i];
#pragma unroll
        for (int c4 = 0; c4 < 8; c4++) {
            float4 w = sW3f4[i * 8 + c4];
            acc[c4 * 4 + 0] += v * w.x; acc[c4 * 4 + 1] += v * w.y;
            acc[c4 * 4 + 2] += v * w.z; acc[c4 * 4 + 3] += v * w.w;
        }
    }
#pragma unroll
    for (int c4 = 0; c4 < 8; c4++) {
        float4 wa = sW3x4[c4], wb = sW3x4[8 + c4], wc = sW3x4[16 + c4];
        acc[c4 * 4 + 0] += fx0 * wa.x + fx1 * wb.x + fx2 * wc.x;
        acc[c4 * 4 + 1] += fx0 * wa.y + fx1 * wb.y + fx2 * wc.y;
        acc[c4 * 4 + 2] += fx0 * wa.z + fx1 * wb.z + fx2 * wc.z;
        acc[c4 * 4 + 3] += fx0 * wa.w + fx1 * wb.w + fx2 * wc.w;
    }
    unsigned uh[16];
#pragma unroll
    for (int c2 = 0; c2 < 16; c2++) {
        float a  = fmaxf(acc[2 * c2]     * sS3[2 * c2]     + sB3[2 * c2],     0.f);
        float bb = fmaxf(acc[2 * c2 + 1] * sS3[2 * c2 + 1] + sB3[2 * c2 + 1], 0.f);
        __half2 h = __floats2half2_rn(a, bb);
        uh[c2] = *reinterpret_cast<unsigned*>(&h);
    }
#pragma unroll
    for (int q = 0; q < 4; q++) {
        uint4 o;
        o.x = uh[q * 4 + 0]; o.y = uh[q * 4 + 1]; o.z = uh[q * 4 + 2]; o.w = uh[q * 4 + 3];
        sStage[t * 5 + q] = o;
    }
    __syncthreads();

    // coalesced uint4 writeout
    uint4* outp = g_preh4 + (size_t)gp0 * 4;
#pragma unroll
    for (int r = 0; r < 4; r++) {
        int i = r * 128 + t;             // i = p*4 + q
        outp[i] = sStage[(i >> 2) * 5 + (i & 3)];
    }
}

// ---------------------------------------------------------------------------
// K4: fp16 gather-max (4 lanes/point, uint4=16B -> 8 pts/warp-instr),
// then final 64->32 MLP with f32x2 FMA + 2-point weight amortization.
// (Round-3 version, measured 41.7 us.)
// ---------------------------------------------------------------------------
__global__ void __launch_bounds__(512) k_gather_final(
    const float* __restrict__ feature, const int* __restrict__ nidx,
    const float* __restrict__ W4, const float* __restrict__ s4, const float* __restrict__ b4,
    float* __restrict__ out)
{
    __shared__ float4 sW4f4[512];        // W4 64x32
    __shared__ float  sS4[32], sB4[32];
    __shared__ float  featS[128 * 36];
    __shared__ float  fcatS[128 * 36];
    __shared__ float  sOut[128 * 33];
    int t = threadIdx.x;
    sW4f4[t] = ((const float4*)W4)[t];
    if (t < 32) { sS4[t] = s4[t]; sB4[t] = b4[t]; }

    int gp0 = blockIdx.x * 128;
    int b   = gp0 >> 16;
    int n0  = gp0 & (NN - 1);

    // stage feat (coalesced along n)
    const float* fbase = feature + (size_t)b * DD * NN + n0;
#pragma unroll
    for (int r = 0; r < 8; r++) {
        int i = r * 512 + t;             // i = c*128 + p
        int c = i >> 7, p = i & 127;
        featS[p * 36 + c] = fbase[(size_t)c * NN + p];
    }

    // cooperative gather-max: 4 lanes/point, each lane owns 8 fp16 channels
    {
        int lane = t & 31;
        int warp = t >> 5;
        int cl   = lane & 3;
        int p    = warp * 8 + (lane >> 2);
        int gp   = gp0 + p;
        int mul  = g_idx64 ? 2 : 1;
        const int* ib = nidx + (size_t)gp * KK * mul;
        int j0 = ib[cl * mul];
        int j1 = ib[(cl + 4) * mul];
        int j2 = ib[(cl + 8) * mul];
        int j3 = ib[(cl + 12) * mul];
        const uint4* pre4 = g_preh4 + (size_t)b * NN * 4;
        __half2 a0 = __half2half2(__ushort_as_half(0));
        __half2 a1 = a0, a2 = a0, a3 = a0;   // pre >= 0, so 0-init exact
#pragma unroll
        for (int k = 0; k < KK; k++) {
            int jr = (k < 8) ? ((k < 4) ? j0 : j1) : ((k < 12) ? j2 : j3);
            int j  = __shfl_sync(0xffffffffu, jr, k & 3, 4);
            uint4 v = pre4[(size_t)j * 4 + cl];
            a0 = __hmax2(a0, *reinterpret_cast<__half2*>(&v.x));
            a1 = __hmax2(a1, *reinterpret_cast<__half2*>(&v.y));
            a2 = __hmax2(a2, *reinterpret_cast<__half2*>(&v.z));
            a3 = __hmax2(a3, *reinterpret_cast<__half2*>(&v.w));
        }
        float2 f0 = __half22float2(a0), f1 = __half22float2(a1);
        float2 f2 = __half22float2(a2), f3 = __half22float2(a3);
        float4* row = (float4*)(fcatS + p * 36);
        row[cl * 2 + 0] = make_float4(f0.x, f0.y, f1.x, f1.y);
        row[cl * 2 + 1] = make_float4(f2.x, f2.y, f3.x, f3.y);
    }
    __syncthreads();

    // final MLP: 8 ch-group threads x 2 points each (weights read once per pair)
    {
        int pp = (t >> 3) * 2, g = t & 7;
        const ulonglong2* w4u = (const ulonglong2*)sW4f4;
        const float4* fS0 = (const float4*)(featS + pp * 36);
        const float4* fS1 = (const float4*)(featS + (pp + 1) * 36);
        const float4* cS0 = (const float4*)(fcatS + pp * 36);
        const float4* cS1 = (const float4*)(fcatS + (pp + 1) * 36);
        u64 p0lo = 0ull, p0hi = 0ull, p1lo = 0ull, p1hi = 0ull;
#pragma unroll
        for (int i4 = 0; i4 < 16; i4++) {
            float4 f0 = (i4 < 8) ? fS0[i4] : cS0[i4 - 8];
            float4 f1 = (i4 < 8) ? fS1[i4] : cS1[i4 - 8];
            ulonglong2 w0 = w4u[(i4 * 4 + 0) * 8 + g];
            ulonglong2 w1 = w4u[(i4 * 4 + 1) * 8 + g];
            ulonglong2 w2 = w4u[(i4 * 4 + 2) * 8 + g];
            ulonglong2 w3 = w4u[(i4 * 4 + 3) * 8 + g];
            u64 v;
            v = pk2(f0.x, f0.x); p0lo = ffma2(v, w0.x, p0lo); p0hi = ffma2(v, w0.y, p0hi);
            v = pk2(f1.x, f1.x); p1lo = ffma2(v, w0.x, p1lo); p1hi = ffma2(v, w0.y, p1hi);
            v = pk2(f0.y, f0.y); p0lo = ffma2(v, w1.x, p0lo); p0hi = ffma2(v, w1.y, p0hi);
            v = pk2(f1.y, f1.y); p1lo = ffma2(v, w1.x, p1lo); p1hi = ffma2(v, w1.y, p1hi);
            v = pk2(f0.z, f0.z); p0lo = ffma2(v, w2.x, p0lo); p0hi = ffma2(v, w2.y, p0hi);
            v = pk2(f1.z, f1.z); p1lo = ffma2(v, w2.x, p1lo); p1hi = ffma2(v, w2.y, p1hi);
            v = pk2(f0.w, f0.w); p0lo = ffma2(v, w3.x, p0lo); p0hi = ffma2(v, w3.y, p0hi);
            v = pk2(f1.w, f1.w); p1lo = ffma2(v, w3.x, p1lo); p1hi = ffma2(v, w3.y, p1hi);
        }
        int c0 = g * 4;
        float a, bb;
        up2(p0lo, a, bb);
        sOut[pp * 33 + c0 + 0] = fmaxf(a  * sS4[c0 + 0] + sB4[c0 + 0], 0.f);
        sOut[pp * 33 + c0 + 1] = fmaxf(bb * sS4[c0 + 1] + sB4[c0 + 1], 0.f);
        up2(p0hi, a, bb);
        sOut[pp * 33 + c0 + 2] = fmaxf(a  * sS4[c0 + 2] + sB4[c0 + 2], 0.f);
        sOut[pp * 33 + c0 + 3] = fmaxf(bb * sS4[c0 + 3] + sB4[c0 + 3], 0.f);
        up2(p1lo, a, bb);
        sOut[(pp + 1) * 33 + c0 + 0] = fmaxf(a  * sS4[c0 + 0] + sB4[c0 + 0], 0.f);
        sOut[(pp + 1) * 33 + c0 + 1] = fmaxf(bb * sS4[c0 + 1] + sB4[c0 + 1], 0.f);
        up2(p1hi, a, bb);
        sOut[(pp + 1) * 33 + c0 + 2] = fmaxf(a  * sS4[c0 + 2] + sB4[c0 + 2], 0.f);
        sOut[(pp + 1) * 33 + c0 + 3] = fmaxf(bb * sS4[c0 + 3] + sB4[c0 + 3], 0.f);
    }
    __syncthreads();

    // coalesced writeout
    float* ob = out + (size_t)b * DD * NN + n0;
#pragma unroll
    for (int r = 0; r < 8; r++) {
        int i = r * 512 + t;             // i = c*128 + p
        int c = i >> 7, pw = i & 127;
        ob[(size_t)c * NN + pw] = sOut[pw * 33 + c];
    }
}

// ---------------------------------------------------------------------------

extern "C" void kernel_launch(void* const* d_in, const int* in_sizes, int n_in,
                              void* d_out, int out_size) {
    const float* feature = (const float*)d_in[0];
    const float* xyz     = (const float*)d_in[1];
    const int*   nidx    = (const int*)d_in[2];
    const float* tW1 = (const float*)d_in[3];  const float* ts1 = (const float*)d_in[4];  const float* tb1 = (const float*)d_in[5];
    const float* tW2 = (const float*)d_in[6];  const float* ts2 = (const float*)d_in[7];  const float* tb2 = (const float*)d_in[8];
    const float* tW3 = (const float*)d_in[9];  const float* ts3 = (const float*)d_in[10]; const float* tb3 = (const float*)d_in[11];
    const float* tW4 = (const float*)d_in[12]; const float* tb4 = (const float*)d_in[13];
    const float* W1  = (const float*)d_in[14]; const float* s1  = (const float*)d_in[15]; const float* b1  = (const float*)d_in[16];
    const float* W2  = (const float*)d_in[17]; const float* s2  = (const float*)d_in[18]; const float* b2  = (const float*)d_in[19];
    const float* W3  = (const float*)d_in[20]; const float* s3  = (const float*)d_in[21]; const float* b3  = (const float*)d_in[22];
    const float* W4  = (const float*)d_in[23]; const float* s4  = (const float*)d_in[24]; const float* b4  = (const float*)d_in[25];
    float* out = (float*)d_out;

    k_tnet_reduce<<<128, 256>>>(xyz, tW1, ts1, tb1, tW2, ts2, tb2);
    k_tnet_head<<<BB, 64>>>(tW3, ts3, tb3, tW4, tb4, nidx);
    k_pointwise<<<(BB * NN) / 128, 128>>>(feature, xyz, W1, s1, b1, W2, s2, b2, W3, s3, b3);
    k_gather_final<<<(BB * NN) / 128, 512>>>(feature, nidx, W4, s4, b4, out);
}